// round 1
// baseline (speedup 1.0000x reference)
#include <cuda_runtime.h>
#include <math.h>

#define N_INST 512
#define L      512
#define VOCAB  50000
#define EMB    128
#define NF     128
#define HID    384
#define ATT    128
#define NCLS   53

// ---------------- scratch (static device globals; no runtime alloc) ---------
__device__ float g_Bmat[EMB * HID];                 // [e][c], c = k*128 + f
__device__ float g_proj[(size_t)VOCAB * HID];       // [v][c]
__device__ float g_H[N_INST * HID];                 // pooled features
__device__ float g_scores[N_INST];
__device__ float g_attn[N_INST];

// ---------------- K0: transpose conv_w (F,E,K) -> Bmat (E, K*128+F) --------
__global__ void k0_transpose(const float* __restrict__ conv_w) {
    int idx = blockIdx.x * blockDim.x + threadIdx.x;
    if (idx >= EMB * HID) return;
    int e = idx / HID;
    int c = idx % HID;
    int kt = c >> 7;       // 0..2
    int f  = c & 127;
    g_Bmat[idx] = conv_w[(f * EMB + e) * 3 + kt];
}

// ---------------- K1: proj GEMM  C[v][c] = sum_e emb[v][e] * Bmat[e][c] ----
// M=50000, N=384, K=128.  BM=64, BN=64, BK=16, 256 threads, 4x4 microtile.
__global__ __launch_bounds__(256) void k1_gemm(const float* __restrict__ A) {
    const int BM = 64, BN = 64, BK = 16;
    __shared__ float As[BK][BM];
    __shared__ float Bs[BK][BN];

    int m0 = blockIdx.y * BM;
    int c0 = blockIdx.x * BN;
    int tid = threadIdx.x;
    int tx = tid % 16;     // col group (4 cols each)
    int ty = tid / 16;     // row group (4 rows each)

    // load-thread mapping
    int arow = tid / 4;    // 0..63
    int acg  = tid % 4;    // k chunk of 4
    int brow = tid / 16;   // 0..15 (k)
    int bcg  = tid % 16;   // col chunk of 4

    float acc[4][4];
#pragma unroll
    for (int i = 0; i < 4; i++)
#pragma unroll
        for (int j = 0; j < 4; j++) acc[i][j] = 0.f;

    for (int k0 = 0; k0 < EMB; k0 += BK) {
        // A tile (guard M), store transposed As[k][m]
        int gm = m0 + arow;
        float4 av = make_float4(0.f, 0.f, 0.f, 0.f);
        if (gm < VOCAB) av = *(const float4*)&A[(size_t)gm * EMB + k0 + acg * 4];
        As[acg * 4 + 0][arow] = av.x;
        As[acg * 4 + 1][arow] = av.y;
        As[acg * 4 + 2][arow] = av.z;
        As[acg * 4 + 3][arow] = av.w;
        // B tile (always in-bounds)
        float4 bv = *(const float4*)&g_Bmat[(k0 + brow) * HID + c0 + bcg * 4];
        *(float4*)&Bs[brow][bcg * 4] = bv;
        __syncthreads();

#pragma unroll
        for (int k = 0; k < BK; k++) {
            float4 a = *(float4*)&As[k][ty * 4];
            float4 b = *(float4*)&Bs[k][tx * 4];
            float av4[4] = {a.x, a.y, a.z, a.w};
            float bv4[4] = {b.x, b.y, b.z, b.w};
#pragma unroll
            for (int i = 0; i < 4; i++)
#pragma unroll
                for (int j = 0; j < 4; j++) acc[i][j] += av4[i] * bv4[j];
        }
        __syncthreads();
    }

#pragma unroll
    for (int i = 0; i < 4; i++) {
        int gm = m0 + ty * 4 + i;
        if (gm < VOCAB) {
            float4 v = make_float4(acc[i][0], acc[i][1], acc[i][2], acc[i][3]);
            *(float4*)&g_proj[(size_t)gm * HID + c0 + tx * 4] = v;
        }
    }
}

// ---------------- K2: gather + 3-tap sum + relu + piecewise max pool -------
// One block per instance, 128 threads (one per filter f).
__global__ __launch_bounds__(128) void k2_pool(const int* __restrict__ ids_g,
                                               const int* __restrict__ pe1,
                                               const int* __restrict__ pe2,
                                               const float* __restrict__ conv_b) {
    int n = blockIdx.x;
    int f = threadIdx.x;
    __shared__ int ids[L];
    for (int i = f; i < L; i += 128) ids[i] = ids_g[n * L + i];
    __syncthreads();

    int p1 = pe1[n], p2 = pe2[n];
    int e1 = min(p1, p2), e2 = max(p1, p2);
    e1 = max(0, min(e1, L));
    e2 = max(0, min(e2, L));
    if (e1 == e2) e2 = min(e1 + 1, L);
    int end1 = (e1 > 0) ? e1 : 1;

    float bias = conv_b[f];
    float m1 = 0.f, m2 = 0.f, m3 = 0.f;  // relu => segment maxes >= 0; segments nonempty

    // token triples: s0 (tap k=0), s1 (k=1), s2 (k=2) of each token
    float c0[8], c1[8], c2[8], n0[8], n1[8], n2[8];
    float pm0 = 0.f;  // slice0 of token (base-1); token -1 is zero padding

#pragma unroll
    for (int j = 0; j < 8; j++) {
        const float* p = &g_proj[(size_t)ids[j] * HID];
        c0[j] = __ldg(p + f);
        c1[j] = __ldg(p + 128 + f);
        c2[j] = __ldg(p + 256 + f);
    }

    for (int base = 0; base < L; base += 8) {
        // batched prefetch of next 8 tokens (24 independent LDG in flight)
#pragma unroll
        for (int j = 0; j < 8; j++) {
            int tok = base + 8 + j;
            if (tok < L) {
                const float* p = &g_proj[(size_t)ids[tok] * HID];
                n0[j] = __ldg(p + f);
                n1[j] = __ldg(p + 128 + f);
                n2[j] = __ldg(p + 256 + f);
            } else {
                n0[j] = 0.f; n1[j] = 0.f; n2[j] = 0.f;
            }
        }
#pragma unroll
        for (int j = 0; j < 8; j++) {
            float s0prev = (j == 0) ? pm0 : c0[j - 1];   // token l-1, tap 0
            float s1cur  = c1[j];                         // token l,   tap 1
            float s2next = (j == 7) ? n2[0] : c2[j + 1];  // token l+1, tap 2
            float y = fmaxf(bias + s0prev + s1cur + s2next, 0.f);
            int l = base + j;
            if (l < end1)             m1 = fmaxf(m1, y);
            if (l >= e1 && l < e2)    m2 = fmaxf(m2, y);
            bool in3 = (e2 < L) ? (l >= e2) : (l == L - 1);
            if (in3)                  m3 = fmaxf(m3, y);
        }
        pm0 = c0[7];
#pragma unroll
        for (int j = 0; j < 8; j++) { c0[j] = n0[j]; c1[j] = n1[j]; c2[j] = n2[j]; }
    }

    g_H[n * HID + f]       = m1;
    g_H[n * HID + 128 + f] = m2;
    g_H[n * HID + 256 + f] = m3;
}

// ---------------- K3: scores[n] = sum_a tanh(H[n]·W_w[a] + Wb[a]) * u[a] ---
__global__ __launch_bounds__(128) void k3_scores(const float* __restrict__ Ww,
                                                 const float* __restrict__ Wb,
                                                 const float* __restrict__ u) {
    int n = blockIdx.x;
    int tid = threadIdx.x;
    __shared__ float Hs[HID];
    for (int i = tid; i < HID; i += 128) Hs[i] = g_H[n * HID + i];
    __syncthreads();

    int lane = tid & 31, w = tid >> 5;  // 4 warps
    float ssum = 0.f;
    for (int i = 0; i < 32; i++) {
        int a = w * 32 + i;
        const float* wr = &Ww[a * HID];
        float part = 0.f;
#pragma unroll
        for (int h = 0; h < 12; h++)
            part += Hs[lane + h * 32] * __ldg(wr + lane + h * 32);
#pragma unroll
        for (int off = 16; off; off >>= 1)
            part += __shfl_down_sync(0xffffffffu, part, off);
        if (lane == 0) ssum += tanhf(part + Wb[a]) * u[a];
    }
    __shared__ float warpsum[4];
    if (lane == 0) warpsum[w] = ssum;
    __syncthreads();
    if (tid == 0) g_scores[n] = warpsum[0] + warpsum[1] + warpsum[2] + warpsum[3];
}

// ---------------- K4: softmax over 512 scores ------------------------------
__global__ __launch_bounds__(512) void k4_softmax(float* __restrict__ out) {
    int tid = threadIdx.x;
    float s = g_scores[tid];
    __shared__ float red[16];
    __shared__ float bmax, bsum;

    float v = s;
#pragma unroll
    for (int off = 16; off; off >>= 1) v = fmaxf(v, __shfl_xor_sync(0xffffffffu, v, off));
    if ((tid & 31) == 0) red[tid >> 5] = v;
    __syncthreads();
    if (tid == 0) {
        float m = red[0];
        for (int i = 1; i < 16; i++) m = fmaxf(m, red[i]);
        bmax = m;
    }
    __syncthreads();

    float e = expf(s - bmax);
    float sv = e;
#pragma unroll
    for (int off = 16; off; off >>= 1) sv += __shfl_xor_sync(0xffffffffu, sv, off);
    __syncthreads();
    if ((tid & 31) == 0) red[tid >> 5] = sv;
    __syncthreads();
    if (tid == 0) {
        float t = 0.f;
        for (int i = 0; i < 16; i++) t += red[i];
        bsum = t;
    }
    __syncthreads();

    float a = e / bsum;
    g_attn[tid] = a;
    out[NCLS + tid] = a;
}

// ---------------- K5: h_bag = attn @ H ; logits = h_bag @ fc_w^T + fc_b ----
__global__ __launch_bounds__(384) void k5_out(const float* __restrict__ fc_w,
                                              const float* __restrict__ fc_b,
                                              float* __restrict__ out) {
    __shared__ float attn_s[N_INST];
    __shared__ float hb[HID];
    int tid = threadIdx.x;
    for (int i = tid; i < N_INST; i += 384) attn_s[i] = g_attn[i];
    __syncthreads();

    float acc = 0.f;
#pragma unroll 4
    for (int nn = 0; nn < N_INST; nn++)
        acc += attn_s[nn] * g_H[nn * HID + tid];
    hb[tid] = acc;
    __syncthreads();

    int w = tid >> 5, lane = tid & 31;  // 12 warps
    for (int t = w; t < NCLS; t += 12) {
        float part = 0.f;
#pragma unroll
        for (int c = lane; c < HID; c += 32)
            part += hb[c] * __ldg(&fc_w[t * HID + c]);
#pragma unroll
        for (int off = 16; off; off >>= 1)
            part += __shfl_down_sync(0xffffffffu, part, off);
        if (lane == 0) out[t] = part + fc_b[t];
    }
}

// ---------------- launch ----------------------------------------------------
extern "C" void kernel_launch(void* const* d_in, const int* in_sizes, int n_in,
                              void* d_out, int out_size) {
    const int*   char_ids = (const int*)d_in[0];
    const int*   pe1      = (const int*)d_in[1];
    const int*   pe2      = (const int*)d_in[2];
    const float* emb      = (const float*)d_in[3];
    const float* conv_w   = (const float*)d_in[4];
    const float* conv_b   = (const float*)d_in[5];
    const float* W_w      = (const float*)d_in[6];
    const float* W_b      = (const float*)d_in[7];
    const float* u_w      = (const float*)d_in[8];
    const float* fc_w     = (const float*)d_in[9];
    const float* fc_b     = (const float*)d_in[10];
    float* out = (float*)d_out;

    k0_transpose<<<(EMB * HID + 255) / 256, 256>>>(conv_w);
    k1_gemm<<<dim3(HID / 64, (VOCAB + 63) / 64), 256>>>(emb);
    k2_pool<<<N_INST, 128>>>(char_ids, pe1, pe2, conv_b);
    k3_scores<<<N_INST, 128>>>(W_w, W_b, u_w);
    k4_softmax<<<1, 512>>>(out);
    k5_out<<<1, 384>>>(fc_w, fc_b, out);
}

// round 2
// speedup vs baseline: 1.0786x; 1.0786x over previous
#include <cuda_runtime.h>
#include <cuda_bf16.h>
#include <math.h>
#include <stdint.h>

#define N_INST 512
#define L      512
#define VOCAB  50000
#define EMB    128
#define NF     128
#define HID    384
#define ATT    128
#define NCLS   53

// ---------------- scratch (static device globals; no runtime alloc) ---------
__device__ __nv_bfloat16 g_Ahi[(size_t)VOCAB * EMB];
__device__ __nv_bfloat16 g_Alo[(size_t)VOCAB * EMB];
__device__ __nv_bfloat16 g_Bhi[HID * EMB];          // [c][e]
__device__ __nv_bfloat16 g_Blo[HID * EMB];
__device__ float g_proj[(size_t)VOCAB * HID];       // [v][c], c = k*128 + f
__device__ float g_H[N_INST * HID];
__device__ float g_scores[N_INST];
__device__ float g_attn[N_INST];

// ---------------- prep: split emb into bf16 hi/lo ---------------------------
__global__ void k_split_emb(const float* __restrict__ emb) {
    int i = blockIdx.x * blockDim.x + threadIdx.x;
    if (i >= VOCAB * EMB) return;
    float a = emb[i];
    __nv_bfloat16 h = __float2bfloat16(a);
    g_Ahi[i] = h;
    g_Alo[i] = __float2bfloat16(a - __bfloat162float(h));
}

// ---------------- prep: conv_w (F,E,K) -> B [c][e] hi/lo bf16 --------------
__global__ void k_split_B(const float* __restrict__ conv_w) {
    int idx = blockIdx.x * blockDim.x + threadIdx.x;
    if (idx >= HID * EMB) return;
    int c = idx >> 7;          // 0..383
    int e = idx & 127;
    int f = c & 127;
    int kt = c >> 7;           // 0..2
    float w = conv_w[(f * EMB + e) * 3 + kt];
    __nv_bfloat16 h = __float2bfloat16(w);
    g_Bhi[c * EMB + e] = h;
    g_Blo[c * EMB + e] = __float2bfloat16(w - __bfloat162float(h));
}

// ---------------- K1: tensor-core proj GEMM --------------------------------
// proj[v][c] = emb[v][:] . B[c][:]  via 3-pass bf16 split (hi*hi+hi*lo+lo*hi)
// CTA tile 128x128, full K=128 in smem, 4 warps each 64x64.
#define SROW 136   // padded bf16 row stride (272 B) -> conflict-free frag LDS
#define K1_SMEM (4 * 128 * SROW * 2)

#define MMA_BF16(d, a, b) \
    asm volatile("mma.sync.aligned.m16n8k16.row.col.f32.bf16.bf16.f32 " \
        "{%0,%1,%2,%3}, {%4,%5,%6,%7}, {%8,%9}, {%0,%1,%2,%3};" \
        : "+f"(d[0]), "+f"(d[1]), "+f"(d[2]), "+f"(d[3]) \
        : "r"(a[0]), "r"(a[1]), "r"(a[2]), "r"(a[3]), "r"(b[0]), "r"(b[1]))

__global__ __launch_bounds__(128, 1) void k1_tc() {
    extern __shared__ __nv_bfloat16 sm_[];
    __nv_bfloat16* As_hi = sm_;
    __nv_bfloat16* As_lo = sm_ + 128 * SROW;
    __nv_bfloat16* Bs_hi = sm_ + 2 * 128 * SROW;
    __nv_bfloat16* Bs_lo = sm_ + 3 * 128 * SROW;

    int tid = threadIdx.x;
    int m0 = blockIdx.y * 128;
    int c0 = blockIdx.x * 128;

    // global -> smem (int4 = 8 bf16)
    int4 zero4 = make_int4(0, 0, 0, 0);
    for (int i = tid; i < 2048; i += 128) {
        int row = i >> 4, cc = i & 15;
        int gm = m0 + row;
        int4 vh = zero4, vl = zero4;
        if (gm < VOCAB) {
            vh = *(const int4*)&g_Ahi[(size_t)gm * EMB + cc * 8];
            vl = *(const int4*)&g_Alo[(size_t)gm * EMB + cc * 8];
        }
        *(int4*)&As_hi[row * SROW + cc * 8] = vh;
        *(int4*)&As_lo[row * SROW + cc * 8] = vl;
        int gc = c0 + row;  // always < 384
        *(int4*)&Bs_hi[row * SROW + cc * 8] = *(const int4*)&g_Bhi[gc * EMB + cc * 8];
        *(int4*)&Bs_lo[row * SROW + cc * 8] = *(const int4*)&g_Blo[gc * EMB + cc * 8];
    }
    __syncthreads();

    int lane = tid & 31, g = lane >> 2, t = lane & 3;
    int wid = tid >> 5, wm = wid & 1, wn = wid >> 1;
    int mbase = wm * 64, nbase = wn * 64;

    float acc[4][8][4];
#pragma unroll
    for (int mi = 0; mi < 4; mi++)
#pragma unroll
        for (int nj = 0; nj < 8; nj++)
#pragma unroll
            for (int q = 0; q < 4; q++) acc[mi][nj][q] = 0.f;

    for (int ks = 0; ks < 8; ks++) {
        int k16 = ks * 16;
        uint32_t ah[4][4], bh[8][2], bl[8][2], al[4][4];
#pragma unroll
        for (int mi = 0; mi < 4; mi++) {
            int r0 = mbase + mi * 16 + g;
            ah[mi][0] = *(const uint32_t*)&As_hi[r0 * SROW + k16 + t * 2];
            ah[mi][1] = *(const uint32_t*)&As_hi[(r0 + 8) * SROW + k16 + t * 2];
            ah[mi][2] = *(const uint32_t*)&As_hi[r0 * SROW + k16 + 8 + t * 2];
            ah[mi][3] = *(const uint32_t*)&As_hi[(r0 + 8) * SROW + k16 + 8 + t * 2];
        }
#pragma unroll
        for (int nj = 0; nj < 8; nj++) {
            int n0i = nbase + nj * 8 + g;
            bh[nj][0] = *(const uint32_t*)&Bs_hi[n0i * SROW + k16 + t * 2];
            bh[nj][1] = *(const uint32_t*)&Bs_hi[n0i * SROW + k16 + 8 + t * 2];
        }
        // pass 1: hi * hi
#pragma unroll
        for (int mi = 0; mi < 4; mi++)
#pragma unroll
            for (int nj = 0; nj < 8; nj++) MMA_BF16(acc[mi][nj], ah[mi], bh[nj]);
        // pass 2: hi * lo
#pragma unroll
        for (int nj = 0; nj < 8; nj++) {
            int n0i = nbase + nj * 8 + g;
            bl[nj][0] = *(const uint32_t*)&Bs_lo[n0i * SROW + k16 + t * 2];
            bl[nj][1] = *(const uint32_t*)&Bs_lo[n0i * SROW + k16 + 8 + t * 2];
        }
#pragma unroll
        for (int mi = 0; mi < 4; mi++)
#pragma unroll
            for (int nj = 0; nj < 8; nj++) MMA_BF16(acc[mi][nj], ah[mi], bl[nj]);
        // pass 3: lo * hi
#pragma unroll
        for (int mi = 0; mi < 4; mi++) {
            int r0 = mbase + mi * 16 + g;
            al[mi][0] = *(const uint32_t*)&As_lo[r0 * SROW + k16 + t * 2];
            al[mi][1] = *(const uint32_t*)&As_lo[(r0 + 8) * SROW + k16 + t * 2];
            al[mi][2] = *(const uint32_t*)&As_lo[r0 * SROW + k16 + 8 + t * 2];
            al[mi][3] = *(const uint32_t*)&As_lo[(r0 + 8) * SROW + k16 + 8 + t * 2];
        }
#pragma unroll
        for (int mi = 0; mi < 4; mi++)
#pragma unroll
            for (int nj = 0; nj < 8; nj++) MMA_BF16(acc[mi][nj], al[mi], bh[nj]);
    }

    // epilogue
#pragma unroll
    for (int mi = 0; mi < 4; mi++) {
#pragma unroll
        for (int nj = 0; nj < 8; nj++) {
            int r = m0 + mbase + mi * 16 + g;
            int ccol = c0 + nbase + nj * 8 + t * 2;
            if (r < VOCAB) {
                float2 v0 = make_float2(acc[mi][nj][0], acc[mi][nj][1]);
                *(float2*)&g_proj[(size_t)r * HID + ccol] = v0;
            }
            if (r + 8 < VOCAB) {
                float2 v1 = make_float2(acc[mi][nj][2], acc[mi][nj][3]);
                *(float2*)&g_proj[(size_t)(r + 8) * HID + ccol] = v1;
            }
        }
    }
}

// ---------------- K2: gather + 3-tap sum + relu + piecewise max pool -------
__global__ __launch_bounds__(128) void k2_pool(const int* __restrict__ ids_g,
                                               const int* __restrict__ pe1,
                                               const int* __restrict__ pe2,
                                               const float* __restrict__ conv_b) {
    int n = blockIdx.x;
    int f = threadIdx.x;
    __shared__ int ids[L];
    for (int i = f; i < L; i += 128) ids[i] = ids_g[n * L + i];
    __syncthreads();

    int p1 = pe1[n], p2 = pe2[n];
    int e1 = min(p1, p2), e2 = max(p1, p2);
    e1 = max(0, min(e1, L));
    e2 = max(0, min(e2, L));
    if (e1 == e2) e2 = min(e1 + 1, L);
    int end1 = (e1 > 0) ? e1 : 1;

    float bias = conv_b[f];
    float m1 = 0.f, m2 = 0.f, m3 = 0.f;

    float c0[8], c1[8], c2[8], n0[8], n1[8], n2[8];
    float pm0 = 0.f;

#pragma unroll
    for (int j = 0; j < 8; j++) {
        const float* p = &g_proj[(size_t)ids[j] * HID];
        c0[j] = __ldg(p + f);
        c1[j] = __ldg(p + 128 + f);
        c2[j] = __ldg(p + 256 + f);
    }

    for (int base = 0; base < L; base += 8) {
#pragma unroll
        for (int j = 0; j < 8; j++) {
            int tok = base + 8 + j;
            if (tok < L) {
                const float* p = &g_proj[(size_t)ids[tok] * HID];
                n0[j] = __ldg(p + f);
                n1[j] = __ldg(p + 128 + f);
                n2[j] = __ldg(p + 256 + f);
            } else {
                n0[j] = 0.f; n1[j] = 0.f; n2[j] = 0.f;
            }
        }
#pragma unroll
        for (int j = 0; j < 8; j++) {
            float s0prev = (j == 0) ? pm0 : c0[j - 1];
            float s1cur  = c1[j];
            float s2next = (j == 7) ? n2[0] : c2[j + 1];
            float y = fmaxf(bias + s0prev + s1cur + s2next, 0.f);
            int l = base + j;
            if (l < end1)             m1 = fmaxf(m1, y);
            if (l >= e1 && l < e2)    m2 = fmaxf(m2, y);
            bool in3 = (e2 < L) ? (l >= e2) : (l == L - 1);
            if (in3)                  m3 = fmaxf(m3, y);
        }
        pm0 = c0[7];
#pragma unroll
        for (int j = 0; j < 8; j++) { c0[j] = n0[j]; c1[j] = n1[j]; c2[j] = n2[j]; }
    }

    g_H[n * HID + f]       = m1;
    g_H[n * HID + 128 + f] = m2;
    g_H[n * HID + 256 + f] = m3;
}

// ---------------- K3: batched attention scores -----------------------------
// 64 blocks x 8 instances; stage W_w chunks in smem (traffic 100MB -> 12.5MB)
__global__ __launch_bounds__(256) void k3_scores(const float* __restrict__ Ww,
                                                 const float* __restrict__ Wb,
                                                 const float* __restrict__ u) {
    int n0 = blockIdx.x * 8;
    __shared__ float Hs[8][HID];
    __shared__ float Wws[128][33];
    __shared__ float red[2][4][4];

    int tid = threadIdx.x;
    for (int i = tid; i < 8 * HID; i += 256)
        Hs[i / HID][i % HID] = g_H[(n0 + i / HID) * HID + (i % HID)];
    __syncthreads();

    int a = tid & 127;
    int half = tid >> 7;
    float acc0 = 0.f, acc1 = 0.f, acc2 = 0.f, acc3 = 0.f;

    for (int c = 0; c < 12; c++) {
        for (int i = tid; i < 128 * 32; i += 256) {
            int r = i >> 5, j = i & 31;
            Wws[r][j] = Ww[r * HID + c * 32 + j];
        }
        __syncthreads();
#pragma unroll
        for (int j = 0; j < 32; j++) {
            float wv = Wws[a][j];
            int h = c * 32 + j;
            acc0 += Hs[half * 4 + 0][h] * wv;
            acc1 += Hs[half * 4 + 1][h] * wv;
            acc2 += Hs[half * 4 + 2][h] * wv;
            acc3 += Hs[half * 4 + 3][h] * wv;
        }
        __syncthreads();
    }

    float wb = Wb[a], uv = u[a];
    float e0 = tanhf(acc0 + wb) * uv;
    float e1 = tanhf(acc1 + wb) * uv;
    float e2 = tanhf(acc2 + wb) * uv;
    float e3 = tanhf(acc3 + wb) * uv;
#pragma unroll
    for (int off = 16; off; off >>= 1) {
        e0 += __shfl_down_sync(0xffffffffu, e0, off);
        e1 += __shfl_down_sync(0xffffffffu, e1, off);
        e2 += __shfl_down_sync(0xffffffffu, e2, off);
        e3 += __shfl_down_sync(0xffffffffu, e3, off);
    }
    int lane = tid & 31;
    int wih = (tid >> 5) & 3;
    if (lane == 0) {
        red[half][0][wih] = e0;
        red[half][1][wih] = e1;
        red[half][2][wih] = e2;
        red[half][3][wih] = e3;
    }
    __syncthreads();
    if (tid < 8) {
        int h2 = tid >> 2, q = tid & 3;
        g_scores[n0 + h2 * 4 + q] =
            red[h2][q][0] + red[h2][q][1] + red[h2][q][2] + red[h2][q][3];
    }
}

// ---------------- K4: softmax over 512 scores ------------------------------
__global__ __launch_bounds__(512) void k4_softmax(float* __restrict__ out) {
    int tid = threadIdx.x;
    float s = g_scores[tid];
    __shared__ float red[16];
    __shared__ float bmax, bsum;

    float v = s;
#pragma unroll
    for (int off = 16; off; off >>= 1) v = fmaxf(v, __shfl_xor_sync(0xffffffffu, v, off));
    if ((tid & 31) == 0) red[tid >> 5] = v;
    __syncthreads();
    if (tid == 0) {
        float m = red[0];
        for (int i = 1; i < 16; i++) m = fmaxf(m, red[i]);
        bmax = m;
    }
    __syncthreads();

    float e = expf(s - bmax);
    float sv = e;
#pragma unroll
    for (int off = 16; off; off >>= 1) sv += __shfl_xor_sync(0xffffffffu, sv, off);
    __syncthreads();
    if ((tid & 31) == 0) red[tid >> 5] = sv;
    __syncthreads();
    if (tid == 0) {
        float t = 0.f;
        for (int i = 0; i < 16; i++) t += red[i];
        bsum = t;
    }
    __syncthreads();

    float a = e / bsum;
    g_attn[tid] = a;
    out[NCLS + tid] = a;
}

// ---------------- K5: h_bag = attn @ H ; logits = h_bag @ fc_w^T + fc_b ----
__global__ __launch_bounds__(384) void k5_out(const float* __restrict__ fc_w,
                                              const float* __restrict__ fc_b,
                                              float* __restrict__ out) {
    __shared__ float attn_s[N_INST];
    __shared__ float hb[HID];
    int tid = threadIdx.x;
    for (int i = tid; i < N_INST; i += 384) attn_s[i] = g_attn[i];
    __syncthreads();

    float acc = 0.f;
#pragma unroll 4
    for (int nn = 0; nn < N_INST; nn++)
        acc += attn_s[nn] * g_H[nn * HID + tid];
    hb[tid] = acc;
    __syncthreads();

    int w = tid >> 5, lane = tid & 31;
    for (int t = w; t < NCLS; t += 12) {
        float part = 0.f;
#pragma unroll
        for (int c = lane; c < HID; c += 32)
            part += hb[c] * __ldg(&fc_w[t * HID + c]);
#pragma unroll
        for (int off = 16; off; off >>= 1)
            part += __shfl_down_sync(0xffffffffu, part, off);
        if (lane == 0) out[t] = part + fc_b[t];
    }
}

// ---------------- launch ----------------------------------------------------
extern "C" void kernel_launch(void* const* d_in, const int* in_sizes, int n_in,
                              void* d_out, int out_size) {
    const int*   char_ids = (const int*)d_in[0];
    const int*   pe1      = (const int*)d_in[1];
    const int*   pe2      = (const int*)d_in[2];
    const float* emb      = (const float*)d_in[3];
    const float* conv_w   = (const float*)d_in[4];
    const float* conv_b   = (const float*)d_in[5];
    const float* W_w      = (const float*)d_in[6];
    const float* W_b      = (const float*)d_in[7];
    const float* u_w      = (const float*)d_in[8];
    const float* fc_w     = (const float*)d_in[9];
    const float* fc_b     = (const float*)d_in[10];
    float* out = (float*)d_out;

    static bool attr_set = false;
    if (!attr_set) {
        cudaFuncSetAttribute(k1_tc, cudaFuncAttributeMaxDynamicSharedMemorySize, K1_SMEM);
        attr_set = true;
    }

    k_split_emb<<<(VOCAB * EMB + 255) / 256, 256>>>(emb);
    k_split_B<<<(HID * EMB + 255) / 256, 256>>>(conv_w);
    k1_tc<<<dim3(HID / 128, (VOCAB + 127) / 128), 128, K1_SMEM>>>();
    k2_pool<<<N_INST, 128>>>(char_ids, pe1, pe2, conv_b);
    k3_scores<<<N_INST / 8, 256>>>(W_w, W_b, u_w);
    k4_softmax<<<1, 512>>>(out);
    k5_out<<<1, 384>>>(fc_w, fc_b, out);
}

// round 4
// speedup vs baseline: 1.3569x; 1.2581x over previous
#include <cuda_runtime.h>
#include <cuda_bf16.h>
#include <cuda_fp16.h>
#include <math.h>
#include <stdint.h>

#define N_INST 512
#define L      512
#define VOCAB  50000
#define EMB    128
#define NF     128
#define HID    384
#define ATT    128
#define NCLS   53

// ---------------- scratch (static device globals; no runtime alloc) ---------
__device__ __nv_bfloat16 g_Ahi[(size_t)VOCAB * EMB];
__device__ __nv_bfloat16 g_Alo[(size_t)VOCAB * EMB];
__device__ __nv_bfloat16 g_Bhi[HID * EMB];          // [c][e]
__device__ __nv_bfloat16 g_Blo[HID * EMB];
__device__ __half g_projh[(size_t)VOCAB * HID];     // [v][c], c = k*128 + f (fp16)
__device__ float g_H[N_INST * HID];
__device__ float g_scores[N_INST];
__device__ float g_attn[N_INST];

// ---------------- prep: split emb into bf16 hi/lo ---------------------------
__global__ void k_split_emb(const float* __restrict__ emb) {
    int i = blockIdx.x * blockDim.x + threadIdx.x;
    if (i >= VOCAB * EMB) return;
    float a = emb[i];
    __nv_bfloat16 h = __float2bfloat16(a);
    g_Ahi[i] = h;
    g_Alo[i] = __float2bfloat16(a - __bfloat162float(h));
}

// conv_w (F,E,K) -> B [c][e] hi/lo bf16, c = kt*128 + f
__global__ void k_split_B(const float* __restrict__ conv_w) {
    int idx = blockIdx.x * blockDim.x + threadIdx.x;
    if (idx >= HID * EMB) return;
    int c = idx >> 7;
    int e = idx & 127;
    int f = c & 127;
    int kt = c >> 7;
    float w = conv_w[(f * EMB + e) * 3 + kt];
    __nv_bfloat16 h = __float2bfloat16(w);
    g_Bhi[c * EMB + e] = h;
    g_Blo[c * EMB + e] = __float2bfloat16(w - __bfloat162float(h));
}

// ---------------- K1: spill-free mma.sync proj GEMM ------------------------
// C[v][c] = emb[v][:] . B[c][:], 3-pass bf16 split (hi*hi + hi*lo + lo*hi).
// CTA tile 128(M) x 128(N), full K=128 in smem. 8 warps as 4(M) x 2(N),
// warp tile 32x64 -> acc[2][8][4] = 64 regs; fragment buffers reused across
// passes so peak live regs ~110 (round-2 version spilled at ~210+).
#define SROW 136   // padded bf16 row stride (272 B), conflict-free
#define K1_SMEM (4 * 128 * SROW * 2)

#define MMA_BF16(d, a, b) \
    asm volatile("mma.sync.aligned.m16n8k16.row.col.f32.bf16.bf16.f32 " \
        "{%0,%1,%2,%3}, {%4,%5,%6,%7}, {%8,%9}, {%0,%1,%2,%3};" \
        : "+f"(d[0]), "+f"(d[1]), "+f"(d[2]), "+f"(d[3]) \
        : "r"(a[0]), "r"(a[1]), "r"(a[2]), "r"(a[3]), "r"(b[0]), "r"(b[1]))

__global__ __launch_bounds__(256, 1) void k1_hmma() {
    extern __shared__ __nv_bfloat16 sm_[];
    __nv_bfloat16* As_hi = sm_;
    __nv_bfloat16* As_lo = sm_ + 128 * SROW;
    __nv_bfloat16* Bs_hi = sm_ + 2 * 128 * SROW;
    __nv_bfloat16* Bs_lo = sm_ + 3 * 128 * SROW;

    int tid = threadIdx.x;
    int m0 = blockIdx.y * 128;
    int c0 = blockIdx.x * 128;

    const int4 z4 = make_int4(0, 0, 0, 0);
    for (int i = tid; i < 2048; i += 256) {          // 128 rows x 16 int4
        int row = i >> 4, kc = i & 15, k = kc * 8;
        int gm = m0 + row;
        int4 vh = z4, vl = z4;
        if (gm < VOCAB) {
            vh = *(const int4*)&g_Ahi[(size_t)gm * EMB + k];
            vl = *(const int4*)&g_Alo[(size_t)gm * EMB + k];
        }
        *(int4*)&As_hi[row * SROW + k] = vh;
        *(int4*)&As_lo[row * SROW + k] = vl;
        int gc = c0 + row;                           // < 384 always
        *(int4*)&Bs_hi[row * SROW + k] = *(const int4*)&g_Bhi[gc * EMB + k];
        *(int4*)&Bs_lo[row * SROW + k] = *(const int4*)&g_Blo[gc * EMB + k];
    }
    __syncthreads();

    int lane = tid & 31, g = lane >> 2, t = lane & 3;
    int wid = tid >> 5;
    int mbase = (wid & 3) * 32;
    int nbase = (wid >> 2) * 64;

    float acc[2][8][4];
#pragma unroll
    for (int mi = 0; mi < 2; mi++)
#pragma unroll
        for (int nj = 0; nj < 8; nj++)
#pragma unroll
            for (int q = 0; q < 4; q++) acc[mi][nj][q] = 0.f;

    for (int ks = 0; ks < 8; ks++) {
        int k16 = ks * 16;
        uint32_t a[2][4], b[8][2];
        // ---- pass 1: hi * hi ----
#pragma unroll
        for (int mi = 0; mi < 2; mi++) {
            int r0 = mbase + mi * 16 + g;
            a[mi][0] = *(const uint32_t*)&As_hi[r0 * SROW + k16 + t * 2];
            a[mi][1] = *(const uint32_t*)&As_hi[(r0 + 8) * SROW + k16 + t * 2];
            a[mi][2] = *(const uint32_t*)&As_hi[r0 * SROW + k16 + 8 + t * 2];
            a[mi][3] = *(const uint32_t*)&As_hi[(r0 + 8) * SROW + k16 + 8 + t * 2];
        }
#pragma unroll
        for (int nj = 0; nj < 8; nj++) {
            int n0i = nbase + nj * 8 + g;
            b[nj][0] = *(const uint32_t*)&Bs_hi[n0i * SROW + k16 + t * 2];
            b[nj][1] = *(const uint32_t*)&Bs_hi[n0i * SROW + k16 + 8 + t * 2];
        }
#pragma unroll
        for (int mi = 0; mi < 2; mi++)
#pragma unroll
            for (int nj = 0; nj < 8; nj++) MMA_BF16(acc[mi][nj], a[mi], b[nj]);
        // ---- pass 2: hi * lo (reuse b regs) ----
#pragma unroll
        for (int nj = 0; nj < 8; nj++) {
            int n0i = nbase + nj * 8 + g;
            b[nj][0] = *(const uint32_t*)&Bs_lo[n0i * SROW + k16 + t * 2];
            b[nj][1] = *(const uint32_t*)&Bs_lo[n0i * SROW + k16 + 8 + t * 2];
        }
#pragma unroll
        for (int mi = 0; mi < 2; mi++)
#pragma unroll
            for (int nj = 0; nj < 8; nj++) MMA_BF16(acc[mi][nj], a[mi], b[nj]);
        // ---- pass 3: lo * hi (reuse a regs, reload b = hi) ----
#pragma unroll
        for (int mi = 0; mi < 2; mi++) {
            int r0 = mbase + mi * 16 + g;
            a[mi][0] = *(const uint32_t*)&As_lo[r0 * SROW + k16 + t * 2];
            a[mi][1] = *(const uint32_t*)&As_lo[(r0 + 8) * SROW + k16 + t * 2];
            a[mi][2] = *(const uint32_t*)&As_lo[r0 * SROW + k16 + 8 + t * 2];
            a[mi][3] = *(const uint32_t*)&As_lo[(r0 + 8) * SROW + k16 + 8 + t * 2];
        }
#pragma unroll
        for (int nj = 0; nj < 8; nj++) {
            int n0i = nbase + nj * 8 + g;
            b[nj][0] = *(const uint32_t*)&Bs_hi[n0i * SROW + k16 + t * 2];
            b[nj][1] = *(const uint32_t*)&Bs_hi[n0i * SROW + k16 + 8 + t * 2];
        }
#pragma unroll
        for (int mi = 0; mi < 2; mi++)
#pragma unroll
            for (int nj = 0; nj < 8; nj++) MMA_BF16(acc[mi][nj], a[mi], b[nj]);
    }

    // epilogue: fp16 half2 stores
#pragma unroll
    for (int mi = 0; mi < 2; mi++) {
#pragma unroll
        for (int nj = 0; nj < 8; nj++) {
            int r = m0 + mbase + mi * 16 + g;
            int cc = c0 + nbase + nj * 8 + t * 2;
            if (r < VOCAB)
                *(__half2*)&g_projh[(size_t)r * HID + cc] =
                    __floats2half2_rn(acc[mi][nj][0], acc[mi][nj][1]);
            if (r + 8 < VOCAB)
                *(__half2*)&g_projh[(size_t)(r + 8) * HID + cc] =
                    __floats2half2_rn(acc[mi][nj][2], acc[mi][nj][3]);
        }
    }
}

// ---------------- K2: fp16 gather + 3-tap + relu + piecewise max pool ------
// 256 threads: f2 = tid&63 covers filters {2f2, 2f2+1}; q = tid>>6 covers
// sequence quarter [q*128, q*128+128).
__global__ __launch_bounds__(256) void k2_pool(const int* __restrict__ ids_g,
                                               const int* __restrict__ pe1,
                                               const int* __restrict__ pe2,
                                               const float* __restrict__ conv_b) {
    int n = blockIdx.x;
    int tid = threadIdx.x;
    int f2 = tid & 63, q = tid >> 6;
    __shared__ int ids[L];
    __shared__ float2 part[3][4][64];
    for (int i = tid; i < L; i += 256) ids[i] = ids_g[n * L + i];
    __syncthreads();

    int p1 = pe1[n], p2 = pe2[n];
    int e1 = min(p1, p2), e2 = max(p1, p2);
    e1 = max(0, min(e1, L));
    e2 = max(0, min(e2, L));
    if (e1 == e2) e2 = min(e1 + 1, L);
    int end1 = (e1 > 0) ? e1 : 1;

    float b0 = conv_b[2 * f2], b1 = conv_b[2 * f2 + 1];
    float2 m1 = make_float2(0.f, 0.f), m2 = m1, m3 = m1;
    int t0 = q * 128;
    int col = 2 * f2;

    for (int base = t0; base < t0 + 128; base += 8) {
        uint32_t p0[8], pc[8], p2v[8];
#pragma unroll
        for (int j = 0; j < 8; j++) {
            int l = base + j;
            p0[j]  = (l > 0)     ? *(const uint32_t*)&g_projh[(size_t)ids[l - 1] * HID + col]       : 0u;
            pc[j]  =               *(const uint32_t*)&g_projh[(size_t)ids[l]     * HID + 128 + col];
            p2v[j] = (l < L - 1) ? *(const uint32_t*)&g_projh[(size_t)ids[l + 1] * HID + 256 + col] : 0u;
        }
#pragma unroll
        for (int j = 0; j < 8; j++) {
            float2 v0 = __half22float2(*(__half2*)&p0[j]);
            float2 v1 = __half22float2(*(__half2*)&pc[j]);
            float2 v2 = __half22float2(*(__half2*)&p2v[j]);
            float y0 = fmaxf(b0 + v0.x + v1.x + v2.x, 0.f);
            float y1 = fmaxf(b1 + v0.y + v1.y + v2.y, 0.f);
            int l = base + j;
            if (l < end1)          { m1.x = fmaxf(m1.x, y0); m1.y = fmaxf(m1.y, y1); }
            if (l >= e1 && l < e2) { m2.x = fmaxf(m2.x, y0); m2.y = fmaxf(m2.y, y1); }
            bool in3 = (e2 < L) ? (l >= e2) : (l == L - 1);
            if (in3)               { m3.x = fmaxf(m3.x, y0); m3.y = fmaxf(m3.y, y1); }
        }
    }
    part[0][q][f2] = m1;
    part[1][q][f2] = m2;
    part[2][q][f2] = m3;
    __syncthreads();
    if (q == 0) {
#pragma unroll
        for (int s = 0; s < 3; s++) {
            float2 r = part[s][0][f2];
#pragma unroll
            for (int qq = 1; qq < 4; qq++) {
                float2 v = part[s][qq][f2];
                r.x = fmaxf(r.x, v.x);
                r.y = fmaxf(r.y, v.y);
            }
            g_H[n * HID + s * 128 + col]     = r.x;
            g_H[n * HID + s * 128 + col + 1] = r.y;
        }
    }
}

// ---------------- K3: batched attention scores -----------------------------
__global__ __launch_bounds__(256) void k3_scores(const float* __restrict__ Ww,
                                                 const float* __restrict__ Wb,
                                                 const float* __restrict__ u) {
    int n0 = blockIdx.x * 8;
    __shared__ float Hs[8][HID];
    __shared__ float Wws[128][33];
    __shared__ float red[2][4][4];

    int tid = threadIdx.x;
    for (int i = tid; i < 8 * HID; i += 256)
        Hs[i / HID][i % HID] = g_H[(n0 + i / HID) * HID + (i % HID)];
    __syncthreads();

    int a = tid & 127;
    int half = tid >> 7;
    float acc0 = 0.f, acc1 = 0.f, acc2 = 0.f, acc3 = 0.f;

    for (int c = 0; c < 12; c++) {
        for (int i = tid; i < 128 * 32; i += 256) {
            int r = i >> 5, j = i & 31;
            Wws[r][j] = Ww[r * HID + c * 32 + j];
        }
        __syncthreads();
#pragma unroll
        for (int j = 0; j < 32; j++) {
            float wv = Wws[a][j];
            int h = c * 32 + j;
            acc0 += Hs[half * 4 + 0][h] * wv;
            acc1 += Hs[half * 4 + 1][h] * wv;
            acc2 += Hs[half * 4 + 2][h] * wv;
            acc3 += Hs[half * 4 + 3][h] * wv;
        }
        __syncthreads();
    }

    float wb = Wb[a], uv = u[a];
    float e0 = tanhf(acc0 + wb) * uv;
    float e1 = tanhf(acc1 + wb) * uv;
    float e2 = tanhf(acc2 + wb) * uv;
    float e3 = tanhf(acc3 + wb) * uv;
#pragma unroll
    for (int off = 16; off; off >>= 1) {
        e0 += __shfl_down_sync(0xffffffffu, e0, off);
        e1 += __shfl_down_sync(0xffffffffu, e1, off);
        e2 += __shfl_down_sync(0xffffffffu, e2, off);
        e3 += __shfl_down_sync(0xffffffffu, e3, off);
    }
    int lane = tid & 31;
    int wih = (tid >> 5) & 3;
    if (lane == 0) {
        red[half][0][wih] = e0;
        red[half][1][wih] = e1;
        red[half][2][wih] = e2;
        red[half][3][wih] = e3;
    }
    __syncthreads();
    if (tid < 8) {
        int h2 = tid >> 2, qq = tid & 3;
        g_scores[n0 + h2 * 4 + qq] =
            red[h2][qq][0] + red[h2][qq][1] + red[h2][qq][2] + red[h2][qq][3];
    }
}

// ---------------- K4: softmax ------------------------------------------------
__global__ __launch_bounds__(512) void k4_softmax(float* __restrict__ out) {
    int tid = threadIdx.x;
    float s = g_scores[tid];
    __shared__ float red[16];
    __shared__ float bmax, bsum;

    float v = s;
#pragma unroll
    for (int off = 16; off; off >>= 1) v = fmaxf(v, __shfl_xor_sync(0xffffffffu, v, off));
    if ((tid & 31) == 0) red[tid >> 5] = v;
    __syncthreads();
    if (tid == 0) {
        float m = red[0];
        for (int i = 1; i < 16; i++) m = fmaxf(m, red[i]);
        bmax = m;
    }
    __syncthreads();

    float e = expf(s - bmax);
    float sv = e;
#pragma unroll
    for (int off = 16; off; off >>= 1) sv += __shfl_xor_sync(0xffffffffu, sv, off);
    __syncthreads();
    if ((tid & 31) == 0) red[tid >> 5] = sv;
    __syncthreads();
    if (tid == 0) {
        float t = 0.f;
        for (int i = 0; i < 16; i++) t += red[i];
        bsum = t;
    }
    __syncthreads();

    float a = e / bsum;
    g_attn[tid] = a;
    out[NCLS + tid] = a;
}

// ---------------- K5: h_bag + logits ----------------------------------------
__global__ __launch_bounds__(384) void k5_out(const float* __restrict__ fc_w,
                                              const float* __restrict__ fc_b,
                                              float* __restrict__ out) {
    __shared__ float attn_s[N_INST];
    __shared__ float hb[HID];
    int tid = threadIdx.x;
    for (int i = tid; i < N_INST; i += 384) attn_s[i] = g_attn[i];
    __syncthreads();

    float acc = 0.f;
#pragma unroll 4
    for (int nn = 0; nn < N_INST; nn++)
        acc += attn_s[nn] * g_H[nn * HID + tid];
    hb[tid] = acc;
    __syncthreads();

    int w = tid >> 5, lane = tid & 31;
    for (int t = w; t < NCLS; t += 12) {
        float part = 0.f;
#pragma unroll
        for (int c = lane; c < HID; c += 32)
            part += hb[c] * __ldg(&fc_w[t * HID + c]);
#pragma unroll
        for (int off = 16; off; off >>= 1)
            part += __shfl_down_sync(0xffffffffu, part, off);
        if (lane == 0) out[t] = part + fc_b[t];
    }
}

// ---------------- launch ------------------------------------------------------
extern "C" void kernel_launch(void* const* d_in, const int* in_sizes, int n_in,
                              void* d_out, int out_size) {
    const int*   char_ids = (const int*)d_in[0];
    const int*   pe1      = (const int*)d_in[1];
    const int*   pe2      = (const int*)d_in[2];
    const float* emb      = (const float*)d_in[3];
    const float* conv_w   = (const float*)d_in[4];
    const float* conv_b   = (const float*)d_in[5];
    const float* W_w      = (const float*)d_in[6];
    const float* W_b      = (const float*)d_in[7];
    const float* u_w      = (const float*)d_in[8];
    const float* fc_w     = (const float*)d_in[9];
    const float* fc_b     = (const float*)d_in[10];
    float* out = (float*)d_out;

    static bool attr_set = false;
    if (!attr_set) {
        cudaFuncSetAttribute(k1_hmma, cudaFuncAttributeMaxDynamicSharedMemorySize, K1_SMEM);
        attr_set = true;
    }

    k_split_emb<<<(VOCAB * EMB + 255) / 256, 256>>>(emb);
    k_split_B<<<(HID * EMB + 255) / 256, 256>>>(conv_w);
    k1_hmma<<<dim3(HID / 128, (VOCAB + 127) / 128), 256, K1_SMEM>>>();
    k2_pool<<<N_INST, 256>>>(char_ids, pe1, pe2, conv_b);
    k3_scores<<<N_INST / 8, 256>>>(W_w, W_b, u_w);
    k4_softmax<<<1, 512>>>(out);
    k5_out<<<1, 384>>>(fc_w, fc_b, out);
}

// round 5
// speedup vs baseline: 2.1719x; 1.6006x over previous
#include <cuda_runtime.h>
#include <cuda_fp16.h>
#include <math.h>
#include <stdint.h>

#define N_INST 512
#define L      512
#define VOCAB  50000
#define EMB    128
#define NF     128
#define HID    384
#define ATT    128
#define NCLS   53

// ---------------- scratch (static device globals; no runtime alloc) ---------
__device__ __half g_Af[(size_t)VOCAB * EMB];        // emb fp16
__device__ __half g_Bf[HID * EMB];                  // [c][e] fp16, c = kt*128+f
__device__ __half g_projh[(size_t)VOCAB * HID];     // [v][c] fp16
__device__ float g_H[N_INST * HID];
__device__ float g_scores[N_INST];

// ---------------- prep ------------------------------------------------------
__global__ void k_prep_emb(const float* __restrict__ emb) {
    int i = blockIdx.x * blockDim.x + threadIdx.x;
    if (i < VOCAB * EMB) g_Af[i] = __float2half(emb[i]);
}
__global__ void k_prep_B(const float* __restrict__ conv_w) {
    int idx = blockIdx.x * blockDim.x + threadIdx.x;
    if (idx >= HID * EMB) return;
    int c = idx >> 7, e = idx & 127;
    int f = c & 127, kt = c >> 7;
    g_Bf[c * EMB + e] = __float2half(conv_w[(f * EMB + e) * 3 + kt]);
}

// ---------------- K1: single-pass fp16 mma.sync proj GEMM ------------------
// C[v][c] = emb[v][:] . B[c][:].  CTA tile 128x128, full K=128 in smem,
// 8 warps as 4(M) x 2(N), warp tile 32x64. 2 CTAs/SM.
#define SROW 136
#define K1_SMEM (2 * 128 * SROW * 2)

#define MMA_F16(d, a, b) \
    asm volatile("mma.sync.aligned.m16n8k16.row.col.f32.f16.f16.f32 " \
        "{%0,%1,%2,%3}, {%4,%5,%6,%7}, {%8,%9}, {%0,%1,%2,%3};" \
        : "+f"(d[0]), "+f"(d[1]), "+f"(d[2]), "+f"(d[3]) \
        : "r"(a[0]), "r"(a[1]), "r"(a[2]), "r"(a[3]), "r"(b[0]), "r"(b[1]))

__global__ __launch_bounds__(256, 2) void k1_hmma() {
    extern __shared__ __half sm_[];
    __half* As = sm_;
    __half* Bs = sm_ + 128 * SROW;

    int tid = threadIdx.x;
    int m0 = blockIdx.y * 128;
    int c0 = blockIdx.x * 128;

    const int4 z4 = make_int4(0, 0, 0, 0);
    for (int i = tid; i < 2048; i += 256) {          // 128 rows x 16 int4
        int row = i >> 4, k = (i & 15) * 8;
        int gm = m0 + row;
        int4 va = z4;
        if (gm < VOCAB) va = *(const int4*)&g_Af[(size_t)gm * EMB + k];
        *(int4*)&As[row * SROW + k] = va;
        int gc = c0 + row;                           // < 384 always
        *(int4*)&Bs[row * SROW + k] = *(const int4*)&g_Bf[gc * EMB + k];
    }
    __syncthreads();

    int lane = tid & 31, g = lane >> 2, t = lane & 3;
    int wid = tid >> 5;
    int mbase = (wid & 3) * 32;
    int nbase = (wid >> 2) * 64;

    float acc[2][8][4];
#pragma unroll
    for (int mi = 0; mi < 2; mi++)
#pragma unroll
        for (int nj = 0; nj < 8; nj++)
#pragma unroll
            for (int q = 0; q < 4; q++) acc[mi][nj][q] = 0.f;

#pragma unroll
    for (int ks = 0; ks < 8; ks++) {
        int k16 = ks * 16;
        uint32_t a[2][4], b[8][2];
#pragma unroll
        for (int mi = 0; mi < 2; mi++) {
            int r0 = mbase + mi * 16 + g;
            a[mi][0] = *(const uint32_t*)&As[r0 * SROW + k16 + t * 2];
            a[mi][1] = *(const uint32_t*)&As[(r0 + 8) * SROW + k16 + t * 2];
            a[mi][2] = *(const uint32_t*)&As[r0 * SROW + k16 + 8 + t * 2];
            a[mi][3] = *(const uint32_t*)&As[(r0 + 8) * SROW + k16 + 8 + t * 2];
        }
#pragma unroll
        for (int nj = 0; nj < 8; nj++) {
            int n0i = nbase + nj * 8 + g;
            b[nj][0] = *(const uint32_t*)&Bs[n0i * SROW + k16 + t * 2];
            b[nj][1] = *(const uint32_t*)&Bs[n0i * SROW + k16 + 8 + t * 2];
        }
#pragma unroll
        for (int mi = 0; mi < 2; mi++)
#pragma unroll
            for (int nj = 0; nj < 8; nj++) MMA_F16(acc[mi][nj], a[mi], b[nj]);
    }

    // epilogue: fp16 half2 stores
#pragma unroll
    for (int mi = 0; mi < 2; mi++) {
#pragma unroll
        for (int nj = 0; nj < 8; nj++) {
            int r = m0 + mbase + mi * 16 + g;
            int cc = c0 + nbase + nj * 8 + t * 2;
            if (r < VOCAB)
                *(__half2*)&g_projh[(size_t)r * HID + cc] =
                    __floats2half2_rn(acc[mi][nj][0], acc[mi][nj][1]);
            if (r + 8 < VOCAB)
                *(__half2*)&g_projh[(size_t)(r + 8) * HID + cc] =
                    __floats2half2_rn(acc[mi][nj][2], acc[mi][nj][3]);
        }
    }
}

// ---------------- K2: fp16 gather + 3-tap + piecewise max pool -------------
// 256 threads: f4 = tid&31 covers 4 filters (8B loads); part = tid>>5 covers
// 64 tokens. Byte-offset table with token-id-0 sentinel (proj row 0 == 0).
__global__ __launch_bounds__(256) void k2_pool(const int* __restrict__ ids_g,
                                               const int* __restrict__ pe1,
                                               const int* __restrict__ pe2,
                                               const float* __restrict__ conv_b) {
    int n = blockIdx.x;
    int tid = threadIdx.x;
    int f4 = tid & 31, part = tid >> 5;
    __shared__ int S[L + 2];                 // byte offsets, shifted by +1
    __shared__ uint2 pb[3][8][32];
    for (int i = tid; i < L; i += 256) S[i + 1] = ids_g[n * L + i] * (HID * 2);
    if (tid == 0) { S[0] = 0; S[L + 1] = 0; }
    __syncthreads();

    int p1 = pe1[n], p2 = pe2[n];
    int e1 = min(p1, p2), e2 = max(p1, p2);
    e1 = max(0, min(e1, L));
    e2 = max(0, min(e2, L));
    if (e1 == e2) e2 = min(e1 + 1, L);
    int end1 = (e1 > 0) ? e1 : 1;

    __half2 hb0 = __floats2half2_rn(conv_b[4 * f4], conv_b[4 * f4 + 1]);
    __half2 hb1 = __floats2half2_rn(conv_b[4 * f4 + 2], conv_b[4 * f4 + 3]);
    __half2 zz = __floats2half2_rn(0.f, 0.f);
    __half2 m10 = zz, m11 = zz, m20 = zz, m21 = zz, m30 = zz, m31 = zz;

    const char* base = (const char*)g_projh;
    int coff = f4 * 8;
    int t0 = part * 64;

#pragma unroll 4
    for (int l = t0; l < t0 + 64; l++) {
        uint2 v0 = *(const uint2*)(base + S[l] + coff);             // tap0: tok l-1
        uint2 v1 = *(const uint2*)(base + S[l + 1] + 256 + coff);   // tap1: tok l
        uint2 v2 = *(const uint2*)(base + S[l + 2] + 512 + coff);   // tap2: tok l+1
        __half2 s0 = __hadd2(__hadd2(*(__half2*)&v0.x, *(__half2*)&v1.x),
                             __hadd2(*(__half2*)&v2.x, hb0));
        __half2 s1 = __hadd2(__hadd2(*(__half2*)&v0.y, *(__half2*)&v1.y),
                             __hadd2(*(__half2*)&v2.y, hb1));
        if (l < end1)          { m10 = __hmax2(m10, s0); m11 = __hmax2(m11, s1); }
        if (l >= e1 && l < e2) { m20 = __hmax2(m20, s0); m21 = __hmax2(m21, s1); }
        bool in3 = (e2 < L) ? (l >= e2) : (l == L - 1);
        if (in3)               { m30 = __hmax2(m30, s0); m31 = __hmax2(m31, s1); }
    }
    pb[0][part][f4] = make_uint2(*(uint32_t*)&m10, *(uint32_t*)&m11);
    pb[1][part][f4] = make_uint2(*(uint32_t*)&m20, *(uint32_t*)&m21);
    pb[2][part][f4] = make_uint2(*(uint32_t*)&m30, *(uint32_t*)&m31);
    __syncthreads();

    if (tid < 96) {
        int seg = tid >> 5, fm = tid & 31;
        __half2 r0 = zz, r1 = zz;
#pragma unroll
        for (int q = 0; q < 8; q++) {
            uint2 v = pb[seg][q][fm];
            r0 = __hmax2(r0, *(__half2*)&v.x);
            r1 = __hmax2(r1, *(__half2*)&v.y);
        }
        float2 a = __half22float2(r0), bq = __half22float2(r1);
        *(float4*)&g_H[n * HID + seg * 128 + 4 * fm] = make_float4(a.x, a.y, bq.x, bq.y);
    }
}

// ---------------- K3: batched attention scores -----------------------------
__global__ __launch_bounds__(256) void k3_scores(const float* __restrict__ Ww,
                                                 const float* __restrict__ Wb,
                                                 const float* __restrict__ u) {
    int n0 = blockIdx.x * 8;
    __shared__ float Hs[8][HID];
    __shared__ float Wws[128][33];
    __shared__ float red[2][4][4];

    int tid = threadIdx.x;
    for (int i = tid; i < 8 * HID; i += 256)
        Hs[i / HID][i % HID] = g_H[(n0 + i / HID) * HID + (i % HID)];
    __syncthreads();

    int a = tid & 127;
    int half = tid >> 7;
    float acc0 = 0.f, acc1 = 0.f, acc2 = 0.f, acc3 = 0.f;

    for (int c = 0; c < 12; c++) {
        for (int i = tid; i < 128 * 32; i += 256) {
            int r = i >> 5, j = i & 31;
            Wws[r][j] = Ww[r * HID + c * 32 + j];
        }
        __syncthreads();
#pragma unroll
        for (int j = 0; j < 32; j++) {
            float wv = Wws[a][j];
            int h = c * 32 + j;
            acc0 += Hs[half * 4 + 0][h] * wv;
            acc1 += Hs[half * 4 + 1][h] * wv;
            acc2 += Hs[half * 4 + 2][h] * wv;
            acc3 += Hs[half * 4 + 3][h] * wv;
        }
        __syncthreads();
    }

    float wb = Wb[a], uv = u[a];
    float e0 = tanhf(acc0 + wb) * uv;
    float e1 = tanhf(acc1 + wb) * uv;
    float e2 = tanhf(acc2 + wb) * uv;
    float e3 = tanhf(acc3 + wb) * uv;
#pragma unroll
    for (int off = 16; off; off >>= 1) {
        e0 += __shfl_down_sync(0xffffffffu, e0, off);
        e1 += __shfl_down_sync(0xffffffffu, e1, off);
        e2 += __shfl_down_sync(0xffffffffu, e2, off);
        e3 += __shfl_down_sync(0xffffffffu, e3, off);
    }
    int lane = tid & 31;
    int wih = (tid >> 5) & 3;
    if (lane == 0) {
        red[half][0][wih] = e0;
        red[half][1][wih] = e1;
        red[half][2][wih] = e2;
        red[half][3][wih] = e3;
    }
    __syncthreads();
    if (tid < 8) {
        int h2 = tid >> 2, qq = tid & 3;
        g_scores[n0 + h2 * 4 + qq] =
            red[h2][qq][0] + red[h2][qq][1] + red[h2][qq][2] + red[h2][qq][3];
    }
}

// ---------------- K45: softmax + h_bag + logits ----------------------------
__global__ __launch_bounds__(512) void k45(const float* __restrict__ fc_w,
                                           const float* __restrict__ fc_b,
                                           float* __restrict__ out) {
    int tid = threadIdx.x;
    __shared__ float red[16];
    __shared__ float bmax, bsum;
    __shared__ float attn_s[N_INST];
    __shared__ float hb[HID];

    float s = g_scores[tid];
    float v = s;
#pragma unroll
    for (int off = 16; off; off >>= 1) v = fmaxf(v, __shfl_xor_sync(0xffffffffu, v, off));
    if ((tid & 31) == 0) red[tid >> 5] = v;
    __syncthreads();
    if (tid == 0) {
        float m = red[0];
        for (int i = 1; i < 16; i++) m = fmaxf(m, red[i]);
        bmax = m;
    }
    __syncthreads();

    float e = expf(s - bmax);
    float sv = e;
#pragma unroll
    for (int off = 16; off; off >>= 1) sv += __shfl_xor_sync(0xffffffffu, sv, off);
    __syncthreads();
    if ((tid & 31) == 0) red[tid >> 5] = sv;
    __syncthreads();
    if (tid == 0) {
        float t = 0.f;
        for (int i = 0; i < 16; i++) t += red[i];
        bsum = t;
    }
    __syncthreads();

    float a = e / bsum;
    attn_s[tid] = a;
    out[NCLS + tid] = a;
    __syncthreads();

    if (tid < HID) {
        float acc = 0.f;
#pragma unroll 8
        for (int nn = 0; nn < N_INST; nn++)
            acc += attn_s[nn] * g_H[nn * HID + tid];
        hb[tid] = acc;
    }
    __syncthreads();

    int w = tid >> 5, lane = tid & 31;
    for (int t = w; t < NCLS; t += 16) {
        float part = 0.f;
#pragma unroll
        for (int c = lane; c < HID; c += 32)
            part += hb[c] * __ldg(&fc_w[t * HID + c]);
#pragma unroll
        for (int off = 16; off; off >>= 1)
            part += __shfl_down_sync(0xffffffffu, part, off);
        if (lane == 0) out[t] = part + fc_b[t];
    }
}

// ---------------- launch ------------------------------------------------------
extern "C" void kernel_launch(void* const* d_in, const int* in_sizes, int n_in,
                              void* d_out, int out_size) {
    const int*   char_ids = (const int*)d_in[0];
    const int*   pe1      = (const int*)d_in[1];
    const int*   pe2      = (const int*)d_in[2];
    const float* emb      = (const float*)d_in[3];
    const float* conv_w   = (const float*)d_in[4];
    const float* conv_b   = (const float*)d_in[5];
    const float* W_w      = (const float*)d_in[6];
    const float* W_b      = (const float*)d_in[7];
    const float* u_w      = (const float*)d_in[8];
    const float* fc_w     = (const float*)d_in[9];
    const float* fc_b     = (const float*)d_in[10];
    float* out = (float*)d_out;

    static bool attr_set = false;
    if (!attr_set) {
        cudaFuncSetAttribute(k1_hmma, cudaFuncAttributeMaxDynamicSharedMemorySize, K1_SMEM);
        attr_set = true;
    }

    k_prep_emb<<<(VOCAB * EMB + 255) / 256, 256>>>(emb);
    k_prep_B<<<(HID * EMB + 255) / 256, 256>>>(conv_w);
    k1_hmma<<<dim3(HID / 128, (VOCAB + 127) / 128), 256, K1_SMEM>>>();
    k2_pool<<<N_INST, 256>>>(char_ids, pe1, pe2, conv_b);
    k3_scores<<<N_INST / 8, 256>>>(W_w, W_b, u_w);
    k45<<<1, 512>>>(fc_w, fc_b, out);
}

// round 6
// speedup vs baseline: 2.5508x; 1.1744x over previous
#include <cuda_runtime.h>
#include <cuda_fp16.h>
#include <math.h>
#include <stdint.h>

#define N_INST 512
#define L      512
#define VOCAB  50000
#define EMB    128
#define NF     128
#define HID    384
#define ATT    128
#define NCLS   53

// ---------------- scratch (static device globals; no runtime alloc) ---------
__device__ __half g_Bf[HID * EMB];                  // [c][e] fp16, c = kt*128+f
__device__ __half g_projh[(size_t)VOCAB * HID];     // [v][c] fp16
__device__ float g_H[N_INST * HID];
__device__ float g_scores[N_INST];

// ---------------- prep: conv_w (F,E,K) -> B[c][e] fp16 ---------------------
__global__ void k_prep_B(const float* __restrict__ conv_w) {
    int idx = blockIdx.x * blockDim.x + threadIdx.x;
    if (idx >= HID * EMB) return;
    int c = idx >> 7, e = idx & 127;
    int f = c & 127, kt = c >> 7;
    g_Bf[c * EMB + e] = __float2half(conv_w[(f * EMB + e) * 3 + kt]);
}

// ---------------- K1: fp16-accumulate mma.sync proj GEMM -------------------
// C[v][c] = emb[v][:] . B[c][:]. CTA tile 128(M) x 128(N), K=128 in smem,
// 8 warps as 4(M) x 2(N), warp tile 32x64, fp16 accumulators (32 regs).
// A converted fp32->fp16 in-flight (no prep kernel). 3 CTAs/SM.
#define SROW 136                      // padded half row stride (272 B)
#define K1_SMEM (2 * 128 * SROW * 2)  // 69632 B

#define MMA_F16ACC(d, a, b) \
    asm volatile("mma.sync.aligned.m16n8k16.row.col.f16.f16.f16.f16 " \
        "{%0,%1}, {%2,%3,%4,%5}, {%6,%7}, {%0,%1};" \
        : "+r"(d[0]), "+r"(d[1]) \
        : "r"(a[0]), "r"(a[1]), "r"(a[2]), "r"(a[3]), "r"(b[0]), "r"(b[1]))

__global__ __launch_bounds__(256, 3) void k1_hmma(const float* __restrict__ emb) {
    extern __shared__ __half sm_[];
    __half* As = sm_;
    __half* Bs = sm_ + 128 * SROW;

    int tid = threadIdx.x;
    int m0 = blockIdx.y * 128;
    int c0 = blockIdx.x * 128;

    // A: fp32 emb -> fp16 smem (zero rows past VOCAB); B: fp16 table
    for (int i = tid; i < 2048; i += 256) {          // 128 rows x 16 chunks of 8
        int row = i >> 4, k = (i & 15) * 8;
        int gm = m0 + row;
        uint2 packed0 = make_uint2(0u, 0u), packed1 = make_uint2(0u, 0u);
        if (gm < VOCAB) {
            float4 f0 = *(const float4*)&emb[(size_t)gm * EMB + k];
            float4 f1 = *(const float4*)&emb[(size_t)gm * EMB + k + 4];
            __half2 h0 = __floats2half2_rn(f0.x, f0.y);
            __half2 h1 = __floats2half2_rn(f0.z, f0.w);
            __half2 h2 = __floats2half2_rn(f1.x, f1.y);
            __half2 h3 = __floats2half2_rn(f1.z, f1.w);
            packed0 = make_uint2(*(uint32_t*)&h0, *(uint32_t*)&h1);
            packed1 = make_uint2(*(uint32_t*)&h2, *(uint32_t*)&h3);
        }
        *(uint2*)&As[row * SROW + k]     = packed0;
        *(uint2*)&As[row * SROW + k + 4] = packed1;
        int gc = c0 + row;                           // < 384 always
        *(int4*)&Bs[row * SROW + k] = *(const int4*)&g_Bf[gc * EMB + k];
    }
    __syncthreads();

    int lane = tid & 31, g = lane >> 2, t = lane & 3;
    int wid = tid >> 5;
    int mbase = (wid & 3) * 32;
    int nbase = (wid >> 2) * 64;

    uint32_t acc[2][8][2];
#pragma unroll
    for (int mi = 0; mi < 2; mi++)
#pragma unroll
        for (int nj = 0; nj < 8; nj++) { acc[mi][nj][0] = 0u; acc[mi][nj][1] = 0u; }

#pragma unroll
    for (int ks = 0; ks < 8; ks++) {
        int k16 = ks * 16;
        uint32_t a[2][4], b[8][2];
#pragma unroll
        for (int mi = 0; mi < 2; mi++) {
            int r0 = mbase + mi * 16 + g;
            a[mi][0] = *(const uint32_t*)&As[r0 * SROW + k16 + t * 2];
            a[mi][1] = *(const uint32_t*)&As[(r0 + 8) * SROW + k16 + t * 2];
            a[mi][2] = *(const uint32_t*)&As[r0 * SROW + k16 + 8 + t * 2];
            a[mi][3] = *(const uint32_t*)&As[(r0 + 8) * SROW + k16 + 8 + t * 2];
        }
#pragma unroll
        for (int nj = 0; nj < 8; nj++) {
            int n0i = nbase + nj * 8 + g;
            b[nj][0] = *(const uint32_t*)&Bs[n0i * SROW + k16 + t * 2];
            b[nj][1] = *(const uint32_t*)&Bs[n0i * SROW + k16 + 8 + t * 2];
        }
#pragma unroll
        for (int mi = 0; mi < 2; mi++)
#pragma unroll
            for (int nj = 0; nj < 8; nj++) MMA_F16ACC(acc[mi][nj], a[mi], b[nj]);
    }

    // ---- epilogue: stage C tile in smem (reuse As), coalesced STG ----
    __syncthreads();
    __half* Cs = sm_;                                // 128 x SROW halfs (fits)
#pragma unroll
    for (int mi = 0; mi < 2; mi++)
#pragma unroll
        for (int nj = 0; nj < 8; nj++) {
            int r = mbase + mi * 16 + g;
            int cc = nbase + nj * 8 + t * 2;
            *(uint32_t*)&Cs[r * SROW + cc]       = acc[mi][nj][0];
            *(uint32_t*)&Cs[(r + 8) * SROW + cc] = acc[mi][nj][1];
        }
    __syncthreads();
    {
        int row = tid >> 1, seg = tid & 1;
        int gm = m0 + row;
        if (gm < VOCAB) {
            const int4* src = (const int4*)&Cs[row * SROW + seg * 64];
            int4* dst = (int4*)&g_projh[(size_t)gm * HID + c0 + seg * 64];
#pragma unroll
            for (int j = 0; j < 8; j++) dst[j] = src[j];
        }
    }
}

// ---------------- K2: fp16 gather + 3-tap + piecewise max pool -------------
// 512 threads: f4 = tid&31 covers 4 filters (8B loads); part = tid>>5 covers
// 32 tokens. Byte-offset table with token-id-0 sentinel (proj row 0 == 0).
__global__ __launch_bounds__(512) void k2_pool(const int* __restrict__ ids_g,
                                               const int* __restrict__ pe1,
                                               const int* __restrict__ pe2,
                                               const float* __restrict__ conv_b) {
    int n = blockIdx.x;
    int tid = threadIdx.x;
    int f4 = tid & 31, part = tid >> 5;
    __shared__ int S[L + 2];                 // byte offsets, shifted by +1
    __shared__ uint2 pb[3][16][32];
    for (int i = tid; i < L; i += 512) S[i + 1] = ids_g[n * L + i] * (HID * 2);
    if (tid == 0) { S[0] = 0; S[L + 1] = 0; }
    __syncthreads();

    int p1 = pe1[n], p2 = pe2[n];
    int e1 = min(p1, p2), e2 = max(p1, p2);
    e1 = max(0, min(e1, L));
    e2 = max(0, min(e2, L));
    if (e1 == e2) e2 = min(e1 + 1, L);
    int end1 = (e1 > 0) ? e1 : 1;

    __half2 hb0 = __floats2half2_rn(conv_b[4 * f4], conv_b[4 * f4 + 1]);
    __half2 hb1 = __floats2half2_rn(conv_b[4 * f4 + 2], conv_b[4 * f4 + 3]);
    __half2 zz = __floats2half2_rn(0.f, 0.f);
    __half2 m10 = zz, m11 = zz, m20 = zz, m21 = zz, m30 = zz, m31 = zz;

    const char* base = (const char*)g_projh;
    int coff = f4 * 8;
    int t0 = part * 32;

#pragma unroll 4
    for (int l = t0; l < t0 + 32; l++) {
        uint2 v0 = *(const uint2*)(base + S[l] + coff);             // tap0: tok l-1
        uint2 v1 = *(const uint2*)(base + S[l + 1] + 256 + coff);   // tap1: tok l
        uint2 v2 = *(const uint2*)(base + S[l + 2] + 512 + coff);   // tap2: tok l+1
        __half2 s0 = __hadd2(__hadd2(*(__half2*)&v0.x, *(__half2*)&v1.x),
                             __hadd2(*(__half2*)&v2.x, hb0));
        __half2 s1 = __hadd2(__hadd2(*(__half2*)&v0.y, *(__half2*)&v1.y),
                             __hadd2(*(__half2*)&v2.y, hb1));
        if (l < end1)          { m10 = __hmax2(m10, s0); m11 = __hmax2(m11, s1); }
        if (l >= e1 && l < e2) { m20 = __hmax2(m20, s0); m21 = __hmax2(m21, s1); }
        bool in3 = (e2 < L) ? (l >= e2) : (l == L - 1);
        if (in3)               { m30 = __hmax2(m30, s0); m31 = __hmax2(m31, s1); }
    }
    pb[0][part][f4] = make_uint2(*(uint32_t*)&m10, *(uint32_t*)&m11);
    pb[1][part][f4] = make_uint2(*(uint32_t*)&m20, *(uint32_t*)&m21);
    pb[2][part][f4] = make_uint2(*(uint32_t*)&m30, *(uint32_t*)&m31);
    __syncthreads();

    if (tid < 96) {
        int seg = tid >> 5, fm = tid & 31;
        __half2 r0 = zz, r1 = zz;
#pragma unroll
        for (int q = 0; q < 16; q++) {
            uint2 v = pb[seg][q][fm];
            r0 = __hmax2(r0, *(__half2*)&v.x);
            r1 = __hmax2(r1, *(__half2*)&v.y);
        }
        float2 a = __half22float2(r0), bq = __half22float2(r1);
        *(float4*)&g_H[n * HID + seg * 128 + 4 * fm] = make_float4(a.x, a.y, bq.x, bq.y);
    }
}

// ---------------- K3: batched attention scores -----------------------------
__global__ __launch_bounds__(256) void k3_scores(const float* __restrict__ Ww,
                                                 const float* __restrict__ Wb,
                                                 const float* __restrict__ u) {
    int n0 = blockIdx.x * 8;
    __shared__ float Hs[8][HID];
    __shared__ float Wws[128][33];
    __shared__ float red[2][4][4];

    int tid = threadIdx.x;
    for (int i = tid; i < 8 * HID; i += 256)
        Hs[i / HID][i % HID] = g_H[(n0 + i / HID) * HID + (i % HID)];
    __syncthreads();

    int a = tid & 127;
    int half = tid >> 7;
    float acc0 = 0.f, acc1 = 0.f, acc2 = 0.f, acc3 = 0.f;

    for (int c = 0; c < 12; c++) {
        for (int i = tid; i < 128 * 32; i += 256) {
            int r = i >> 5, j = i & 31;
            Wws[r][j] = Ww[r * HID + c * 32 + j];
        }
        __syncthreads();
#pragma unroll
        for (int j = 0; j < 32; j++) {
            float wv = Wws[a][j];
            int h = c * 32 + j;
            acc0 += Hs[half * 4 + 0][h] * wv;
            acc1 += Hs[half * 4 + 1][h] * wv;
            acc2 += Hs[half * 4 + 2][h] * wv;
            acc3 += Hs[half * 4 + 3][h] * wv;
        }
        __syncthreads();
    }

    float wb = Wb[a], uv = u[a];
    float e0 = tanhf(acc0 + wb) * uv;
    float e1 = tanhf(acc1 + wb) * uv;
    float e2 = tanhf(acc2 + wb) * uv;
    float e3 = tanhf(acc3 + wb) * uv;
#pragma unroll
    for (int off = 16; off; off >>= 1) {
        e0 += __shfl_down_sync(0xffffffffu, e0, off);
        e1 += __shfl_down_sync(0xffffffffu, e1, off);
        e2 += __shfl_down_sync(0xffffffffu, e2, off);
        e3 += __shfl_down_sync(0xffffffffu, e3, off);
    }
    int lane = tid & 31;
    int wih = (tid >> 5) & 3;
    if (lane == 0) {
        red[half][0][wih] = e0;
        red[half][1][wih] = e1;
        red[half][2][wih] = e2;
        red[half][3][wih] = e3;
    }
    __syncthreads();
    if (tid < 8) {
        int h2 = tid >> 2, qq = tid & 3;
        g_scores[n0 + h2 * 4 + qq] =
            red[h2][qq][0] + red[h2][qq][1] + red[h2][qq][2] + red[h2][qq][3];
    }
}

// ---------------- K45: softmax + h_bag + logits ----------------------------
__global__ __launch_bounds__(512) void k45(const float* __restrict__ fc_w,
                                           const float* __restrict__ fc_b,
                                           float* __restrict__ out) {
    int tid = threadIdx.x;
    __shared__ float red[16];
    __shared__ float bmax, bsum;
    __shared__ float attn_s[N_INST];
    __shared__ float hb[HID];

    float s = g_scores[tid];
    float v = s;
#pragma unroll
    for (int off = 16; off; off >>= 1) v = fmaxf(v, __shfl_xor_sync(0xffffffffu, v, off));
    if ((tid & 31) == 0) red[tid >> 5] = v;
    __syncthreads();
    if (tid == 0) {
        float m = red[0];
        for (int i = 1; i < 16; i++) m = fmaxf(m, red[i]);
        bmax = m;
    }
    __syncthreads();

    float e = expf(s - bmax);
    float sv = e;
#pragma unroll
    for (int off = 16; off; off >>= 1) sv += __shfl_xor_sync(0xffffffffu, sv, off);
    __syncthreads();
    if ((tid & 31) == 0) red[tid >> 5] = sv;
    __syncthreads();
    if (tid == 0) {
        float t = 0.f;
        for (int i = 0; i < 16; i++) t += red[i];
        bsum = t;
    }
    __syncthreads();

    float a = e / bsum;
    attn_s[tid] = a;
    out[NCLS + tid] = a;
    __syncthreads();

    if (tid < HID) {
        float acc = 0.f;
#pragma unroll 8
        for (int nn = 0; nn < N_INST; nn++)
            acc += attn_s[nn] * g_H[nn * HID + tid];
        hb[tid] = acc;
    }
    __syncthreads();

    int w = tid >> 5, lane = tid & 31;
    for (int t = w; t < NCLS; t += 16) {
        float part = 0.f;
#pragma unroll
        for (int c = lane; c < HID; c += 32)
            part += hb[c] * __ldg(&fc_w[t * HID + c]);
#pragma unroll
        for (int off = 16; off; off >>= 1)
            part += __shfl_down_sync(0xffffffffu, part, off);
        if (lane == 0) out[t] = part + fc_b[t];
    }
}

// ---------------- launch ------------------------------------------------------
extern "C" void kernel_launch(void* const* d_in, const int* in_sizes, int n_in,
                              void* d_out, int out_size) {
    const int*   char_ids = (const int*)d_in[0];
    const int*   pe1      = (const int*)d_in[1];
    const int*   pe2      = (const int*)d_in[2];
    const float* emb      = (const float*)d_in[3];
    const float* conv_w   = (const float*)d_in[4];
    const float* conv_b   = (const float*)d_in[5];
    const float* W_w      = (const float*)d_in[6];
    const float* W_b      = (const float*)d_in[7];
    const float* u_w      = (const float*)d_in[8];
    const float* fc_w     = (const float*)d_in[9];
    const float* fc_b     = (const float*)d_in[10];
    float* out = (float*)d_out;

    static bool attr_set = false;
    if (!attr_set) {
        cudaFuncSetAttribute(k1_hmma, cudaFuncAttributeMaxDynamicSharedMemorySize, K1_SMEM);
        attr_set = true;
    }

    k_prep_B<<<(HID * EMB + 255) / 256, 256>>>(conv_w);
    k1_hmma<<<dim3(HID / 128, (VOCAB + 127) / 128), 256, K1_SMEM>>>(emb);
    k2_pool<<<N_INST, 512>>>(char_ids, pe1, pe2, conv_b);
    k3_scores<<<N_INST / 8, 256>>>(W_w, W_b, u_w);
    k45<<<1, 512>>>(fc_w, fc_b, out);
}